// round 12
// baseline (speedup 1.0000x reference)
#include <cuda_runtime.h>
#include <cstdint>

// ---------------- problem constants ----------------
constexpr int B_    = 4;
constexpr int T_    = 16;
constexpr int HEADS = 8;
constexpr int HW    = 1024;       // 32*32
constexpr int NSLAB = B_ * T_;    // 64
constexpr float QSCALE = 0.17677669529663687f;

// ---------------- scratch (__device__ globals) ----------------
__device__ float g_q[B_ * HEADS * T_ * 32 * HW];   // [b][head][t][d][hw]
__device__ float g_k[B_ * HEADS * T_ * 32 * HW];
__device__ float g_v[B_ * HEADS * T_ * 32 * HW];
__device__ float g_o[NSLAB * 256 * HW];            // [slab][e][hw]

// ---------------- PTX helpers ----------------
__device__ __forceinline__ uint32_t smem_u32(const void* p) {
    uint32_t a;
    asm("{ .reg .u64 t; cvta.to.shared.u64 t, %1; cvt.u32.u64 %0, t; }" : "=r"(a) : "l"(p));
    return a;
}
__device__ __forceinline__ void cp16(uint32_t s, const void* g) {
    asm volatile("cp.async.cg.shared.global [%0], [%1], 16;" :: "r"(s), "l"(g) : "memory");
}
__device__ __forceinline__ void cp_commit() {
    asm volatile("cp.async.commit_group;" ::: "memory");
}
template <int N>
__device__ __forceinline__ void cp_wait() {
    asm volatile("cp.async.wait_group %0;" :: "n"(N) : "memory");
}
// shared f32 load + convert to tf32 container (RNA)
__device__ __forceinline__ uint32_t ld_tf32(uint32_t addr) {
    float f;
    asm volatile("ld.shared.f32 %0, [%1];" : "=f"(f) : "r"(addr));
    uint32_t u;
    asm("cvt.rna.tf32.f32 %0, %1;" : "=r"(u) : "f"(f));
    return u;
}
__device__ __forceinline__ void mma_tf32(float& c0, float& c1, float& c2, float& c3,
                                         uint32_t a0, uint32_t a1, uint32_t a2,
                                         uint32_t a3, uint32_t b0, uint32_t b1) {
    asm volatile(
        "mma.sync.aligned.m16n8k8.row.col.f32.tf32.tf32.f32 "
        "{%0,%1,%2,%3}, {%4,%5,%6,%7}, {%8,%9}, {%0,%1,%2,%3};"
        : "+f"(c0), "+f"(c1), "+f"(c2), "+f"(c3)
        : "r"(a0), "r"(a1), "r"(a2), "r"(a3), "r"(b0), "r"(b1));
}

// ---------------- SMEM staging layout ----------------
// A tile: 32 k-rows x 128 m floats, row stride 544B (bank: 8*lk+l4 injective)
// B tile: 64 n-rows x 32 k floats,  row stride 144B (bank: 4*l4+lk injective)
constexpr int ASTR  = 544;
constexpr int BSTR  = 144;
constexpr int O_A   = 0;            // 32*544  = 17408
constexpr int O_B   = 17408;        // 64*144  = 9216
constexpr int STAGE = 26624;
constexpr int SMEM_TOTAL = 2 * STAGE;   // 53248 (epilogue cs: 64*132*4=33792 fits)
constexpr int CSTR = 132;

// ================= tf32 tensor-core GEMM =================
// D[m=hw 128][n=o 64] = A[hw,k] * B[o,k]^T, K=256, single-pass tf32.
// A gathered from [k][m] layout (X or O, f32, no transpose kernel needed).
// B = W rows (f32, direct). 128 threads, 4 warps (2m x 2n), 2-stage cp.async.
// EPI 0: q/k/v f32 epilogue (+bias, q*scale). EPI 1: +bias -> Y f32.
template <int EPI>
__global__ __launch_bounds__(128, 4) void tf32_gemm(const float* __restrict__ Xg,
                                                    const float* __restrict__ W,
                                                    const float* __restrict__ bias,
                                                    float* __restrict__ Y) {
    extern __shared__ __align__(16) char smem[];
    const uint32_t sb = smem_u32(smem);
    const int tid  = threadIdx.x;
    const int wid  = tid >> 5;
    const int lane = tid & 31;
    const int wm = wid & 1;     // warp m tile (64 hw rows)
    const int wn = wid >> 1;    // warp n tile (32 o cols)
    const int l4 = lane >> 2;   // 0..7
    const int lk = lane & 3;    // 0..3

    const int slab = blockIdx.z;
    const int hw0  = blockIdx.x * 128;
    const int n0   = blockIdx.y * 64;

    const float* xs = Xg + (size_t)slab * 256 * HW + hw0;   // row k adds HW
    const float* ws = W + (size_t)n0 * 256;                 // row n adds 256

    float acc[4][4][4];
#pragma unroll
    for (int mt = 0; mt < 4; mt++)
#pragma unroll
        for (int nt = 0; nt < 4; nt++)
#pragma unroll
            for (int r = 0; r < 4; r++) acc[mt][nt][r] = 0.0f;

    auto issue = [&](int kt, int s) {
        const uint32_t base = sb + s * STAGE;
        // A: 32 rows x 128 floats = 256 chunks of 16B
#pragma unroll
        for (int i = 0; i < 2; i++) {
            const int chunk = tid + 128 * i;          // row = chunk>>4? no:
            const int row = chunk >> 5;               // 32 chunks (of 16B) per row? 128 floats=512B=32 chunks
            const int c16 = chunk & 31;
            cp16(base + O_A + (uint32_t)(row * ASTR + c16 * 16),
                 xs + (size_t)(kt * 32 + row) * HW + c16 * 4);
        }
#pragma unroll
        for (int i = 2; i < 8; i++) {
            const int chunk = tid + 128 * i;
            const int row = chunk >> 5;
            const int c16 = chunk & 31;
            cp16(base + O_A + (uint32_t)(row * ASTR + c16 * 16),
                 xs + (size_t)(kt * 32 + row) * HW + c16 * 4);
        }
        // B: 64 rows x 32 floats = 8 chunks/row = 512 chunks
#pragma unroll
        for (int i = 0; i < 4; i++) {
            const int chunk = tid + 128 * i;
            const int row = chunk >> 3;
            const int c = chunk & 7;
            cp16(base + O_B + (uint32_t)(row * BSTR + c * 16),
                 ws + (size_t)row * 256 + kt * 32 + c * 4);
        }
    };

    issue(0, 0);
    cp_commit();

    // fragment address components (bytes)
    const uint32_t aFix = (uint32_t)(lk * ASTR + (wm * 64 + l4) * 4);
    const uint32_t bFix = (uint32_t)((wn * 32 + l4) * BSTR + lk * 4);

    uint32_t so = 0;
    for (int kt = 0; kt < 8; kt++) {
        if (kt < 7) {
            issue(kt + 1, (kt + 1) & 1);
            cp_commit();
            cp_wait<1>();
        } else {
            cp_wait<0>();
        }
        __syncthreads();

        const uint32_t Abase = sb + so + O_A + aFix;
        const uint32_t Bbase = sb + so + O_B + bFix;
#pragma unroll
        for (int ks = 0; ks < 4; ks++) {
            const uint32_t ak = Abase + (uint32_t)(ks * 8 * ASTR);
            const uint32_t bk = Bbase + (uint32_t)(ks * 32);
            uint32_t a[4][4], b[4][2];
#pragma unroll
            for (int mt = 0; mt < 4; mt++) {
                const uint32_t am = ak + (uint32_t)(mt * 64);
                a[mt][0] = ld_tf32(am);                      // (m, k)
                a[mt][1] = ld_tf32(am + 32);                 // (m+8, k)
                a[mt][2] = ld_tf32(am + 4 * ASTR);           // (m, k+4)
                a[mt][3] = ld_tf32(am + 4 * ASTR + 32);      // (m+8, k+4)
            }
#pragma unroll
            for (int nt = 0; nt < 4; nt++) {
                const uint32_t bn = bk + (uint32_t)(nt * 8 * BSTR);
                b[nt][0] = ld_tf32(bn);                      // (k, n)
                b[nt][1] = ld_tf32(bn + 16);                 // (k+4, n)
            }
#pragma unroll
            for (int mt = 0; mt < 4; mt++)
#pragma unroll
                for (int nt = 0; nt < 4; nt++)
                    mma_tf32(acc[mt][nt][0], acc[mt][nt][1], acc[mt][nt][2],
                             acc[mt][nt][3], a[mt][0], a[mt][1], a[mt][2],
                             a[mt][3], b[nt][0], b[nt][1]);
        }
        __syncthreads();
        so ^= (uint32_t)STAGE;
    }

    // ---------------- epilogue: transpose through SMEM ----------------
    float* cs = (float*)smem;   // [64 n][CSTR m]
#pragma unroll
    for (int mt = 0; mt < 4; mt++)
#pragma unroll
        for (int nt = 0; nt < 4; nt++) {
            const int n = wn * 32 + nt * 8 + lk * 2;
            const int m = wm * 64 + mt * 16 + l4;
            cs[n * CSTR + m]           = acc[mt][nt][0];
            cs[(n + 1) * CSTR + m]     = acc[mt][nt][1];
            cs[n * CSTR + m + 8]       = acc[mt][nt][2];
            cs[(n + 1) * CSTR + m + 8] = acc[mt][nt][3];
        }
    __syncthreads();

    const int b_ = slab >> 4, t_ = slab & 15;
#pragma unroll
    for (int r = 0; r < 16; r++) {
        const int n = wid * 16 + r;
        const int o = n0 + n;
        float4 v = *(const float4*)&cs[n * CSTR + lane * 4];
        const float bv = bias[o];
        if (EPI == 0) {
            const int which = o >> 8;
            const int head  = (o >> 5) & 7;
            const int d     = o & 31;
            float* dst = (which == 0) ? g_q : (which == 1 ? g_k : g_v);
            const float sc = (which == 0) ? QSCALE : 1.0f;
            v.x = (v.x + bv) * sc; v.y = (v.y + bv) * sc;
            v.z = (v.z + bv) * sc; v.w = (v.w + bv) * sc;
            const size_t off =
                ((size_t)(((b_ * 8 + head) * 16 + t_) * 32 + d)) * 1024 + hw0 + lane * 4;
            *(float4*)(dst + off) = v;
        } else {
            v.x += bv; v.y += bv; v.z += bv; v.w += bv;
            *(float4*)(Y + ((size_t)slab * 256 + o) * 1024 + hw0 + lane * 4) = v;
        }
    }
}

// ================= attention (T=16), all f32 =================
__device__ __forceinline__ unsigned long long pack2(float lo, float hi) {
    unsigned long long r;
    asm("mov.b64 %0, {%1, %2};" : "=l"(r) : "f"(lo), "f"(hi));
    return r;
}
__device__ __forceinline__ void unpack2(unsigned long long p, float& lo, float& hi) {
    asm("mov.b64 {%0, %1}, %2;" : "=f"(lo), "=f"(hi) : "l"(p));
}
__device__ __forceinline__ unsigned long long ffma2(unsigned long long a,
                                                    unsigned long long b,
                                                    unsigned long long c) {
    unsigned long long d;
    asm("fma.rn.f32x2 %0, %1, %2, %3;" : "=l"(d) : "l"(a), "l"(b), "l"(c));
    return d;
}

constexpr int KVP = 512 + 4;
__global__ __launch_bounds__(128) void attn_k(const float* __restrict__ rel_pos) {
    __shared__ __align__(16) float k_s[8][KVP];
    __shared__ __align__(16) float v_s[8][KVP];

    const int bh  = blockIdx.y;            // b*8 + head
    const int hw0 = blockIdx.x * 8;
    const int tid = threadIdx.x;
    const int hwl = tid & 7;
    const int i   = tid >> 3;              // query t 0..15

    const size_t ubase = (size_t)bh * 512 * HW;

    for (int e = tid; e < 4096; e += 128) {
        const int td = e >> 3;
        const int hw = e & 7;
        k_s[hw][td] = g_k[ubase + (size_t)td * HW + hw0 + hw];
        v_s[hw][td] = g_v[ubase + (size_t)td * HW + hw0 + hw];
    }
    __syncthreads();

    unsigned long long qp[16];
    const size_t qbase = ubase + (size_t)i * 32 * HW + hw0 + hwl;
#pragma unroll
    for (int c = 0; c < 16; c++)
        qp[c] = pack2(g_q[qbase + (size_t)(2 * c) * HW],
                      g_q[qbase + (size_t)(2 * c + 1) * HW]);

    const int head = bh & 7;
    const float* rp = rel_pos + head * 256 + i * 16;

    float s[16];
#pragma unroll
    for (int j = 0; j < 16; j++) {
        const ulonglong2* kp = (const ulonglong2*)&k_s[hwl][j * 32];
        unsigned long long acc = 0ull;
#pragma unroll
        for (int c = 0; c < 8; c++) {
            const ulonglong2 kk = kp[c];
            acc = ffma2(qp[2 * c],     kk.x, acc);
            acc = ffma2(qp[2 * c + 1], kk.y, acc);
        }
        float lo, hi;
        unpack2(acc, lo, hi);
        s[j] = lo + hi + rp[j];
    }

    float mx = s[0];
#pragma unroll
    for (int j = 1; j < 16; j++) mx = fmaxf(mx, s[j]);
    float sum = 0.0f;
#pragma unroll
    for (int j = 0; j < 16; j++) { s[j] = expf(s[j] - mx); sum += s[j]; }
    const float inv = 1.0f / sum;

    unsigned long long o2[16];
#pragma unroll
    for (int c = 0; c < 16; c++) o2[c] = 0ull;
#pragma unroll
    for (int j = 0; j < 16; j++) {
        const unsigned long long pp = pack2(s[j], s[j]);
        const ulonglong2* vp = (const ulonglong2*)&v_s[hwl][j * 32];
#pragma unroll
        for (int c = 0; c < 8; c++) {
            const ulonglong2 vv = vp[c];
            o2[2 * c]     = ffma2(pp, vv.x, o2[2 * c]);
            o2[2 * c + 1] = ffma2(pp, vv.y, o2[2 * c + 1]);
        }
    }

    // write f32 output [slab][e][hw] — the [k][m] layout gemm<1> consumes
    const int b_ = bh >> 3;
    const size_t obase =
        ((size_t)((b_ * 16 + i) * 256 + head * 32)) * HW + hw0 + hwl;
#pragma unroll
    for (int c = 0; c < 16; c++) {
        float lo, hi;
        unpack2(o2[c], lo, hi);
        g_o[obase + (size_t)(2 * c) * HW]     = lo * inv;
        g_o[obase + (size_t)(2 * c + 1) * HW] = hi * inv;
    }
}

// ================= host =================
extern "C" void kernel_launch(void* const* d_in, const int* in_sizes, int n_in,
                              void* d_out, int out_size) {
    const float* x       = (const float*)d_in[0];
    const float* rel_pos = (const float*)d_in[1];
    const float* w_qkv   = (const float*)d_in[2];
    const float* b_qkv   = (const float*)d_in[3];
    const float* w_out   = (const float*)d_in[4];
    const float* b_out   = (const float*)d_in[5];
    float* y = (float*)d_out;

    cudaFuncSetAttribute(tf32_gemm<0>, cudaFuncAttributeMaxDynamicSharedMemorySize, SMEM_TOTAL);
    cudaFuncSetAttribute(tf32_gemm<1>, cudaFuncAttributeMaxDynamicSharedMemorySize, SMEM_TOTAL);

    float* o_ptr;
    cudaGetSymbolAddress((void**)&o_ptr, g_o);

    // QKV projection from raw f32 x: grid = (hw 8, o-tiles 12, slabs 64)
    tf32_gemm<0><<<dim3(8, 12, 64), 128, SMEM_TOTAL>>>(x, w_qkv, b_qkv, nullptr);
    // attention (f32 in/out)
    attn_k<<<dim3(128, 32), 128>>>(rel_pos);
    // output projection from g_o: grid = (8, 4, 64)
    tf32_gemm<1><<<dim3(8, 4, 64), 128, SMEM_TOTAL>>>(o_ptr, w_out, b_out, y);
}